// round 1
// baseline (speedup 1.0000x reference)
#include <cuda_runtime.h>
#include <cuda_bf16.h>

// InstantNerf fused MLP, fp32 scalar path with packed fma.rn.f32x2.
// d_in order (metadata): position[N*32], direction[N*3],
//   W1[32*64], b1[64], W2[64*16], b2[16], W3[32*64], b3[64],
//   W4[64*64], b4[64], W5[64*3], b5[3]
// d_out: density [N,16] followed by color [N,3], float32, row-major.

#define FMA2(acc, a2, w2) \
    asm("fma.rn.f32x2 %0, %1, %2, %0;" : "+l"(acc) : "l"(a2), "l"(w2))

__device__ __forceinline__ unsigned long long pack_dup(float x) {
    unsigned long long r;
    asm("mov.b64 %0, {%1, %1};" : "=l"(r) : "f"(x));
    return r;
}

__device__ __forceinline__ void unpack2(unsigned long long v, float& lo, float& hi) {
    asm("mov.b64 {%0, %1}, %2;" : "=f"(lo), "=f"(hi) : "l"(v));
}

// Dense layer: out[OUT] = in[IN] @ W[IN,OUT] + b, optional relu.
// W row-major [IN][OUT] in shared, 16B-aligned rows (OUT % 4 == 0).
template <int IN, int OUT, bool RELU>
__device__ __forceinline__ void dense_layer(const float* in, float* out,
                                            const float* sW, const float* sb) {
    static_assert(OUT % 4 == 0, "OUT must be multiple of 4");
    unsigned long long acc[OUT / 2];
    const ulonglong2* bb = reinterpret_cast<const ulonglong2*>(sb);
#pragma unroll
    for (int j = 0; j < OUT / 4; j++) {
        ulonglong2 b2 = bb[j];
        acc[2 * j] = b2.x;
        acc[2 * j + 1] = b2.y;
    }
#pragma unroll 8
    for (int i = 0; i < IN; i++) {
        unsigned long long a2 = pack_dup(in[i]);
        const ulonglong2* wrow = reinterpret_cast<const ulonglong2*>(sW + i * OUT);
#pragma unroll
        for (int j = 0; j < OUT / 4; j++) {
            ulonglong2 w = wrow[j];
            FMA2(acc[2 * j], a2, w.x);
            FMA2(acc[2 * j + 1], a2, w.y);
        }
    }
#pragma unroll
    for (int j = 0; j < OUT / 2; j++) {
        float lo, hi;
        unpack2(acc[j], lo, hi);
        if (RELU) { lo = fmaxf(lo, 0.0f); hi = fmaxf(hi, 0.0f); }
        out[2 * j] = lo;
        out[2 * j + 1] = hi;
    }
}

// Shared-memory layout (float offsets, all 16-float / 64B aligned)
static constexpr int OW1 = 0;       // 32*64 = 2048
static constexpr int OB1 = 2048;    // 64
static constexpr int OW2 = 2112;    // 64*16 = 1024
static constexpr int OB2 = 3136;    // 16
static constexpr int OW3 = 3152;    // 32*64 = 2048
static constexpr int OB3 = 5200;    // 64
static constexpr int OW4 = 5264;    // 64*64 = 4096
static constexpr int OB4 = 9360;    // 64
static constexpr int OW5 = 9424;    // 64*3 = 192
static constexpr int OB5 = 9616;    // 3
static constexpr int SMEM_FLOATS = 9632;

__global__ void __launch_bounds__(128)
nerf_fused_kernel(const float* __restrict__ position,
                  const float* __restrict__ direction,
                  const float* __restrict__ W1, const float* __restrict__ b1,
                  const float* __restrict__ W2, const float* __restrict__ b2,
                  const float* __restrict__ W3, const float* __restrict__ b3,
                  const float* __restrict__ W4, const float* __restrict__ b4,
                  const float* __restrict__ W5, const float* __restrict__ b5,
                  float* __restrict__ out, int n) {
    __shared__ float sw[SMEM_FLOATS];

    // Cooperative weight staging
    int tid = threadIdx.x;
    for (int i = tid; i < 2048; i += 128) sw[OW1 + i] = W1[i];
    for (int i = tid; i < 64;   i += 128) sw[OB1 + i] = b1[i];
    for (int i = tid; i < 1024; i += 128) sw[OW2 + i] = W2[i];
    for (int i = tid; i < 16;   i += 128) sw[OB2 + i] = b2[i];
    for (int i = tid; i < 2048; i += 128) sw[OW3 + i] = W3[i];
    for (int i = tid; i < 64;   i += 128) sw[OB3 + i] = b3[i];
    for (int i = tid; i < 4096; i += 128) sw[OW4 + i] = W4[i];
    for (int i = tid; i < 64;   i += 128) sw[OB4 + i] = b4[i];
    for (int i = tid; i < 192;  i += 128) sw[OW5 + i] = W5[i];
    for (int i = tid; i < 3;    i += 128) sw[OB5 + i] = b5[i];
    __syncthreads();

    int t = blockIdx.x * 128 + tid;
    if (t >= n) return;

    // ---- Load position [32] (8x float4, warp-contiguous region via L1) ----
    float pin[32];
    {
        const float4* p4 = reinterpret_cast<const float4*>(position + (size_t)t * 32);
#pragma unroll
        for (int i = 0; i < 8; i++) {
            float4 v = p4[i];
            pin[4 * i + 0] = v.x; pin[4 * i + 1] = v.y;
            pin[4 * i + 2] = v.z; pin[4 * i + 3] = v.w;
        }
    }

    // ---- Density MLP: 32 -> 64 (relu) -> 16 ----
    float h[64];
    dense_layer<32, 64, true>(pin, h, sw + OW1, sw + OB1);

    float dens[16];
    dense_layer<64, 16, false>(h, dens, sw + OW2, sw + OB2);

    // Store density [N,16]
    {
        float4* o4 = reinterpret_cast<float4*>(out + (size_t)t * 16);
#pragma unroll
        for (int j = 0; j < 4; j++)
            o4[j] = make_float4(dens[4 * j], dens[4 * j + 1],
                                dens[4 * j + 2], dens[4 * j + 3]);
    }

    // ---- SH degree-4 encoding of direction ----
    float cin[32];
#pragma unroll
    for (int j = 0; j < 16; j++) cin[j] = dens[j];
    {
        const float* d = direction + (size_t)t * 3;
        float x = d[0], y = d[1], z = d[2];
        float xx = x * x, yy = y * y, zz = z * z;
        cin[16 + 0]  = 0.28209479177387814f;
        cin[16 + 1]  = 0.4886025119029199f * y;
        cin[16 + 2]  = 0.4886025119029199f * z;
        cin[16 + 3]  = 0.4886025119029199f * x;
        cin[16 + 4]  = 1.0925484305920792f * x * y;
        cin[16 + 5]  = 1.0925484305920792f * y * z;
        cin[16 + 6]  = 0.9461746957575601f * zz - 0.31539156525252f;
        cin[16 + 7]  = 1.0925484305920792f * x * z;
        cin[16 + 8]  = 0.5462742152960396f * (xx - yy);
        cin[16 + 9]  = 0.5900435899266435f * y * (3.0f * xx - yy);
        cin[16 + 10] = 2.890611442640554f * x * y * z;
        cin[16 + 11] = 0.4570457994644658f * y * (5.0f * zz - 1.0f);
        cin[16 + 12] = 0.3731763325901154f * z * (5.0f * zz - 3.0f);
        cin[16 + 13] = 0.4570457994644658f * x * (5.0f * zz - 1.0f);
        cin[16 + 14] = 1.445305721320277f * z * (xx - yy);
        cin[16 + 15] = 0.5900435899266435f * x * (xx - 3.0f * yy);
    }

    // ---- Color MLP: 32 -> 64 (relu) -> 64 (relu) -> 3 (sigmoid) ----
    float c1[64];
    dense_layer<32, 64, true>(cin, c1, sw + OW3, sw + OB3);
    float c2[64];
    dense_layer<64, 64, true>(c1, c2, sw + OW4, sw + OB4);

    {
        float a0 = sw[OB5 + 0], a1 = sw[OB5 + 1], a2 = sw[OB5 + 2];
#pragma unroll 16
        for (int i = 0; i < 64; i++) {
            float v = c2[i];
            const float* wr = sw + OW5 + i * 3;
            a0 = fmaf(v, wr[0], a0);
            a1 = fmaf(v, wr[1], a1);
            a2 = fmaf(v, wr[2], a2);
        }
        float* co = out + (size_t)n * 16 + (size_t)t * 3;
        co[0] = 1.0f / (1.0f + __expf(-a0));
        co[1] = 1.0f / (1.0f + __expf(-a1));
        co[2] = 1.0f / (1.0f + __expf(-a2));
    }
}

extern "C" void kernel_launch(void* const* d_in, const int* in_sizes, int n_in,
                              void* d_out, int out_size) {
    const float* position = (const float*)d_in[0];
    const float* direction = (const float*)d_in[1];
    const float* W1 = (const float*)d_in[2];
    const float* b1 = (const float*)d_in[3];
    const float* W2 = (const float*)d_in[4];
    const float* b2 = (const float*)d_in[5];
    const float* W3 = (const float*)d_in[6];
    const float* b3 = (const float*)d_in[7];
    const float* W4 = (const float*)d_in[8];
    const float* b4 = (const float*)d_in[9];
    const float* W5 = (const float*)d_in[10];
    const float* b5 = (const float*)d_in[11];
    float* out = (float*)d_out;

    int n = in_sizes[0] / 32;
    int blocks = (n + 127) / 128;
    nerf_fused_kernel<<<blocks, 128>>>(position, direction,
                                       W1, b1, W2, b2, W3, b3, W4, b4, W5, b5,
                                       out, n);
}

// round 4
// speedup vs baseline: 1.7283x; 1.7283x over previous
#include <cuda_runtime.h>
#include <cstdint>

// ============================================================================
// InstantNerf fused MLP via warp-level mma.sync tf32 (m16n8k8), sm_103.
// (tcgen05 unavailable: harness PTX targets compute_103 without 'a'.)
//
// CTA = 256 threads = 8 warps; each warp owns 32 samples (2 x m16).
// Weights staged per-CTA into smem in B-fragment order (LDS.64/frag).
// Activations ping-pong in padded smem (stride 68 floats, conflict-free
// A-fragment loads). No inter-warp synchronization after staging.
// ============================================================================

static constexpr int AST = 68;                  // activation row stride (floats)
static constexpr int ROWS = 256;                // samples per CTA

// ---- smem layout (float offsets) ----
static constexpr int OFF_W1F = 0;               // 4*8*64  = 2048
static constexpr int OFF_W2F = 2048;            // 8*2*64  = 1024
static constexpr int OFF_W3F = 3072;            // 4*8*64  = 2048
static constexpr int OFF_W4F = 5120;            // 8*8*64  = 4096
static constexpr int OFF_W5F = 9216;            // 8*1*64  = 512
static constexpr int OFF_B1  = 9728;            // 64
static constexpr int OFF_B2  = 9792;            // 16
static constexpr int OFF_B3  = 9808;            // 64
static constexpr int OFF_B4  = 9872;            // 64
static constexpr int OFF_B5  = 9936;            // 8
static constexpr int OFF_BUFA = 9952;           // 256*68 = 17408
static constexpr int OFF_BUFB = OFF_BUFA + ROWS * AST;
static constexpr int SMEM_FLOATS = OFF_BUFB + ROWS * AST;   // 44768 -> 179072 B

__device__ __forceinline__ uint32_t f2tf32(float x) {
    uint32_t u;
    asm("cvt.rna.tf32.f32 %0, %1;" : "=r"(u) : "f"(x));
    return u;
}

__device__ __forceinline__ void mma_tf32(float (&d)[4], uint32_t a0, uint32_t a1,
                                         uint32_t a2, uint32_t a3,
                                         uint32_t b0, uint32_t b1) {
    asm volatile(
        "mma.sync.aligned.m16n8k8.row.col.f32.tf32.tf32.f32 "
        "{%0,%1,%2,%3}, {%4,%5,%6,%7}, {%8,%9}, {%0,%1,%2,%3};"
        : "+f"(d[0]), "+f"(d[1]), "+f"(d[2]), "+f"(d[3])
        : "r"(a0), "r"(a1), "r"(a2), "r"(a3), "r"(b0), "r"(b1));
}

// Stage weight matrix W[K][Nreal] (row-major, gmem) into B-fragment order:
// slot s = kstep*NT + ntile holds 64 tf32 words; lane l, half h ->
//   W[kstep*8 + (l&3) + 4h][ntile*8 + (l>>2)]
template <int KT, int NT>
__device__ __forceinline__ void stage_bfrag(uint32_t* dst, const float* W,
                                            int Nreal, int tid) {
    for (int idx = tid; idx < KT * NT * 64; idx += 256) {
        int s = idx >> 6, rem = idx & 63;
        int lane = rem >> 1, half = rem & 1;
        int kstep = s / NT, nt = s - kstep * NT;
        int kk = kstep * 8 + (lane & 3) + half * 4;
        int nn = nt * 8 + (lane >> 2);
        float v = (nn < Nreal) ? W[kk * Nreal + nn] : 0.0f;
        dst[s * 64 + lane * 2 + half] = f2tf32(v);
    }
}

// One dense layer on tensor cores. sA points at the input buffer already
// offset by the column base. acc laid out [m-tile][n-tile][4].
template <int KT, int NT>
__device__ __forceinline__ void run_layer(const uint32_t* __restrict__ sA,
                                          const uint32_t* __restrict__ bfrag,
                                          const float* __restrict__ bias,
                                          int mrow0, int g, int tg, int lane,
                                          float (&acc)[2][NT][4]) {
#pragma unroll
    for (int m = 0; m < 2; m++)
#pragma unroll
        for (int nn = 0; nn < NT; nn++) {
            float2 bb = ((const float2*)bias)[nn * 4 + tg];
            acc[m][nn][0] = bb.x; acc[m][nn][1] = bb.y;
            acc[m][nn][2] = bb.x; acc[m][nn][3] = bb.y;
        }
#pragma unroll
    for (int k = 0; k < KT; k++) {
        uint2 bf[NT];
#pragma unroll
        for (int nn = 0; nn < NT; nn++)
            bf[nn] = ((const uint2*)bfrag)[(k * NT + nn) * 32 + lane];
#pragma unroll
        for (int m = 0; m < 2; m++) {
            const uint32_t* ap = sA + (mrow0 + m * 16 + g) * AST + k * 8 + tg;
            uint32_t a0 = ap[0];
            uint32_t a1 = ap[8 * AST];
            uint32_t a2 = ap[4];
            uint32_t a3 = ap[8 * AST + 4];
#pragma unroll
            for (int nn = 0; nn < NT; nn++)
                mma_tf32(acc[m][nn], a0, a1, a2, a3, bf[nn].x, bf[nn].y);
        }
    }
}

// Epilogue: relu + tf32-convert + store to smem buffer (at column base dst).
template <int NT>
__device__ __forceinline__ void epi_relu_store(float (&acc)[2][NT][4],
                                               uint32_t* dst, int mrow0,
                                               int g, int tg) {
#pragma unroll
    for (int m = 0; m < 2; m++)
#pragma unroll
        for (int nn = 0; nn < NT; nn++) {
            int r0 = mrow0 + m * 16 + g;
            uint2 lo, hi;
            lo.x = f2tf32(fmaxf(acc[m][nn][0], 0.0f));
            lo.y = f2tf32(fmaxf(acc[m][nn][1], 0.0f));
            hi.x = f2tf32(fmaxf(acc[m][nn][2], 0.0f));
            hi.y = f2tf32(fmaxf(acc[m][nn][3], 0.0f));
            *(uint2*)(dst + r0 * AST + nn * 8 + 2 * tg) = lo;
            *(uint2*)(dst + (r0 + 8) * AST + nn * 8 + 2 * tg) = hi;
        }
}

__global__ void __launch_bounds__(256, 1)
nerf_mma_kernel(const float* __restrict__ position,
                const float* __restrict__ direction,
                const float* __restrict__ W1, const float* __restrict__ b1,
                const float* __restrict__ W2, const float* __restrict__ b2,
                const float* __restrict__ W3, const float* __restrict__ b3,
                const float* __restrict__ W4, const float* __restrict__ b4,
                const float* __restrict__ W5, const float* __restrict__ b5,
                float* __restrict__ out, int n) {
    extern __shared__ float smf[];
    uint32_t* smu = (uint32_t*)smf;

    const int tid = threadIdx.x;
    const int lane = tid & 31;
    const int wid = tid >> 5;
    const int g = lane >> 2;       // groupID 0..7
    const int tg = lane & 3;       // thread-in-group 0..3

    // ---- stage weights (fragment order) + biases ----
    stage_bfrag<4, 8>(smu + OFF_W1F, W1, 64, tid);
    stage_bfrag<8, 2>(smu + OFF_W2F, W2, 16, tid);
    stage_bfrag<4, 8>(smu + OFF_W3F, W3, 64, tid);
    stage_bfrag<8, 8>(smu + OFF_W4F, W4, 64, tid);
    stage_bfrag<8, 1>(smu + OFF_W5F, W5, 3, tid);
    if (tid < 64) smf[OFF_B1 + tid] = b1[tid];
    if (tid < 16) smf[OFF_B2 + tid] = b2[tid];
    if (tid < 64) smf[OFF_B3 + tid] = b3[tid];
    if (tid < 64) smf[OFF_B4 + tid] = b4[tid];
    if (tid < 8)  smf[OFF_B5 + tid] = (tid < 3) ? b5[tid] : 0.0f;

    // ---- stage this CTA's inputs: position cols 0..31, SH cols 32..47 ----
    const int base = blockIdx.x * ROWS;
    const int r = base + tid;
    uint32_t* bufA = smu + OFF_BUFA;
    uint32_t* bufB = smu + OFF_BUFB;
    {
        uint32_t* row = bufA + tid * AST;
        if (r < n) {
            const float4* p4 = (const float4*)(position + (size_t)r * 32);
#pragma unroll
            for (int c = 0; c < 8; c++) {
                float4 v = p4[c];
                row[c * 4 + 0] = f2tf32(v.x);
                row[c * 4 + 1] = f2tf32(v.y);
                row[c * 4 + 2] = f2tf32(v.z);
                row[c * 4 + 3] = f2tf32(v.w);
            }
            const float* dp = direction + (size_t)r * 3;
            float x = dp[0], y = dp[1], z = dp[2];
            float xx = x * x, yy = y * y, zz = z * z;
            row[32 + 0]  = f2tf32(0.28209479177387814f);
            row[32 + 1]  = f2tf32(0.4886025119029199f * y);
            row[32 + 2]  = f2tf32(0.4886025119029199f * z);
            row[32 + 3]  = f2tf32(0.4886025119029199f * x);
            row[32 + 4]  = f2tf32(1.0925484305920792f * x * y);
            row[32 + 5]  = f2tf32(1.0925484305920792f * y * z);
            row[32 + 6]  = f2tf32(0.9461746957575601f * zz - 0.31539156525252f);
            row[32 + 7]  = f2tf32(1.0925484305920792f * x * z);
            row[32 + 8]  = f2tf32(0.5462742152960396f * (xx - yy));
            row[32 + 9]  = f2tf32(0.5900435899266435f * y * (3.0f * xx - yy));
            row[32 + 10] = f2tf32(2.890611442640554f * x * y * z);
            row[32 + 11] = f2tf32(0.4570457994644658f * y * (5.0f * zz - 1.0f));
            row[32 + 12] = f2tf32(0.3731763325901154f * z * (5.0f * zz - 3.0f));
            row[32 + 13] = f2tf32(0.4570457994644658f * x * (5.0f * zz - 1.0f));
            row[32 + 14] = f2tf32(1.445305721320277f * z * (xx - yy));
            row[32 + 15] = f2tf32(0.5900435899266435f * x * (xx - 3.0f * yy));
        } else {
#pragma unroll
            for (int c = 0; c < 48; c++) row[c] = 0u;
        }
    }
    __syncthreads();
    // From here on every warp works only on its own 32 rows: no more barriers.

    const int mrow0 = wid * 32;

    // ---- L1: pos[.,0..31] @ W1 -> bufB cols 0..63 (relu) ----
    {
        float acc[2][8][4];
        run_layer<4, 8>(bufA, smu + OFF_W1F, smf + OFF_B1, mrow0, g, tg, lane, acc);
        epi_relu_store<8>(acc, bufB, mrow0, g, tg);
    }

    // ---- L2: bufB @ W2 -> density ; store gmem + bufA cols 16..31 ----
    {
        float acc[2][2][4];
        run_layer<8, 2>(bufB, smu + OFF_W2F, smf + OFF_B2, mrow0, g, tg, lane, acc);
#pragma unroll
        for (int m = 0; m < 2; m++)
#pragma unroll
            for (int nn = 0; nn < 2; nn++) {
                int r0 = mrow0 + m * 16 + g;
                int gr0 = base + r0;
                float2 lo = make_float2(acc[m][nn][0], acc[m][nn][1]);
                float2 hi = make_float2(acc[m][nn][2], acc[m][nn][3]);
                if (gr0 < n)
                    *(float2*)(out + (size_t)gr0 * 16 + nn * 8 + 2 * tg) = lo;
                if (gr0 + 8 < n)
                    *(float2*)(out + (size_t)(gr0 + 8) * 16 + nn * 8 + 2 * tg) = hi;
                uint2 ulo, uhi;
                ulo.x = f2tf32(lo.x); ulo.y = f2tf32(lo.y);
                uhi.x = f2tf32(hi.x); uhi.y = f2tf32(hi.y);
                *(uint2*)(bufA + r0 * AST + 16 + nn * 8 + 2 * tg) = ulo;
                *(uint2*)(bufA + (r0 + 8) * AST + 16 + nn * 8 + 2 * tg) = uhi;
            }
    }

    // ---- L3: bufA cols 16..47 (dens||SH) @ W3 -> bufB (relu) ----
    {
        float acc[2][8][4];
        run_layer<4, 8>(bufA + 16, smu + OFF_W3F, smf + OFF_B3, mrow0, g, tg, lane, acc);
        epi_relu_store<8>(acc, bufB, mrow0, g, tg);
    }

    // ---- L4: bufB @ W4 -> bufA cols 0..63 (relu) ----
    {
        float acc[2][8][4];
        run_layer<8, 8>(bufB, smu + OFF_W4F, smf + OFF_B4, mrow0, g, tg, lane, acc);
        epi_relu_store<8>(acc, bufA, mrow0, g, tg);
    }

    // ---- L5: bufA @ W5 -> color (sigmoid) ----
    {
        float acc[2][1][4];
        run_layer<8, 1>(bufA, smu + OFF_W5F, smf + OFF_B5, mrow0, g, tg, lane, acc);
        float* co = out + (size_t)n * 16;
#pragma unroll
        for (int m = 0; m < 2; m++) {
            int gr0 = base + mrow0 + m * 16 + g;
            float s0 = 1.0f / (1.0f + __expf(-acc[m][0][0]));
            float s1 = 1.0f / (1.0f + __expf(-acc[m][0][1]));
            float s2 = 1.0f / (1.0f + __expf(-acc[m][0][2]));
            float s3 = 1.0f / (1.0f + __expf(-acc[m][0][3]));
            if (tg == 0) {
                if (gr0 < n)     { co[(size_t)gr0 * 3 + 0] = s0;
                                   co[(size_t)gr0 * 3 + 1] = s1; }
                if (gr0 + 8 < n) { co[(size_t)(gr0 + 8) * 3 + 0] = s2;
                                   co[(size_t)(gr0 + 8) * 3 + 1] = s3; }
            } else if (tg == 1) {
                if (gr0 < n)     co[(size_t)gr0 * 3 + 2] = s0;
                if (gr0 + 8 < n) co[(size_t)(gr0 + 8) * 3 + 2] = s2;
            }
        }
    }
}

extern "C" void kernel_launch(void* const* d_in, const int* in_sizes, int n_in,
                              void* d_out, int out_size) {
    const float* position = (const float*)d_in[0];
    const float* direction = (const float*)d_in[1];
    const float* W1 = (const float*)d_in[2];
    const float* b1 = (const float*)d_in[3];
    const float* W2 = (const float*)d_in[4];
    const float* b2 = (const float*)d_in[5];
    const float* W3 = (const float*)d_in[6];
    const float* b3 = (const float*)d_in[7];
    const float* W4 = (const float*)d_in[8];
    const float* b4 = (const float*)d_in[9];
    const float* W5 = (const float*)d_in[10];
    const float* b5 = (const float*)d_in[11];
    float* out = (float*)d_out;

    int n = in_sizes[0] / 32;
    int ntiles = (n + ROWS - 1) / ROWS;
    if (ntiles <= 0) return;
    size_t smem_bytes = (size_t)SMEM_FLOATS * sizeof(float);

    cudaFuncSetAttribute(nerf_mma_kernel,
                         cudaFuncAttributeMaxDynamicSharedMemorySize,
                         (int)smem_bytes);
    nerf_mma_kernel<<<ntiles, 256, smem_bytes>>>(position, direction,
                                                 W1, b1, W2, b2, W3, b3,
                                                 W4, b4, W5, b5, out, n);
}

// round 5
// speedup vs baseline: 4.1604x; 2.4072x over previous
#include <cuda_runtime.h>
#include <cstdint>

// ============================================================================
// InstantNerf fused MLP, warp-level mma.sync tf32 (m16n8k8), sm_103.
// R5: occupancy-focused rework of R4.
//  - Weights pre-converted to B-fragment order in a __device__ global buffer
//    by a prep kernel; main kernel loads them via LDG (L1-resident, ~39KB).
//  - Position A-fragments loaded directly from gmem (lane-mapped LDG).
//  - smem holds only biases + dens||SH buffer (stride 36) + one in-place
//    hidden buffer (stride 68): ~94KB -> 2 CTAs/SM, 14 warps/SM.
//  - 224 threads/CTA (7 warps x 32 rows) so 2 CTAs fit the register file.
// ============================================================================

static constexpr int THREADS = 224;
static constexpr int ROWS = 224;
static constexpr int INS = 36;   // dens||SH row stride (floats): 36%32=4 -> conflict-free A reads
static constexpr int HS  = 68;   // hidden row stride (floats): 68%32=4 -> conflict-free

// smem float offsets
static constexpr int OFF_B1 = 0;      // 64
static constexpr int OFF_B2 = 64;     // 16
static constexpr int OFF_B3 = 80;     // 64
static constexpr int OFF_B4 = 144;    // 64
static constexpr int OFF_B5 = 208;    // 8 (padded)
static constexpr int OFF_IN = 224;            // 224*36 = 8064
static constexpr int OFF_H  = OFF_IN + ROWS * INS;   // 8288
static constexpr int SMEM_FLOATS = OFF_H + ROWS * HS; // 23520 -> 94080 B

// global fragment buffer (word offsets)
static constexpr int W1F = 0;       // 4k x 8n x 64 = 2048
static constexpr int W2F = 2048;    // 8k x 2n x 64 = 1024
static constexpr int W3F = 3072;    // 2048
static constexpr int W4F = 5120;    // 8k x 8n x 64 = 4096
static constexpr int W5F = 9216;    // 8k x 1n x 64 = 512
__device__ uint32_t g_wfrag[9728];

__device__ __forceinline__ uint32_t f2tf32(float x) {
    uint32_t u;
    asm("cvt.rna.tf32.f32 %0, %1;" : "=r"(u) : "f"(x));
    return u;
}

__device__ __forceinline__ void mma_tf32(float (&d)[4], uint32_t a0, uint32_t a1,
                                         uint32_t a2, uint32_t a3,
                                         uint32_t b0, uint32_t b1) {
    asm volatile(
        "mma.sync.aligned.m16n8k8.row.col.f32.tf32.tf32.f32 "
        "{%0,%1,%2,%3}, {%4,%5,%6,%7}, {%8,%9}, {%0,%1,%2,%3};"
        : "+f"(d[0]), "+f"(d[1]), "+f"(d[2]), "+f"(d[3])
        : "r"(a0), "r"(a1), "r"(a2), "r"(a3), "r"(b0), "r"(b1));
}

// ---------------- prep kernel: W[K][Nreal] -> B-fragment order ----------------
// slot s = kstep*NT + ntile; within slot: lane l, half h ->
//   W[kstep*8 + (l&3) + 4h][ntile*8 + (l>>2)]
__device__ __forceinline__ void stage_section(uint32_t* dst, const float* W,
                                              int Nreal, int KT, int NT,
                                              int tid, int ntot) {
    int total = KT * NT * 64;
    for (int idx = tid; idx < total; idx += ntot) {
        int s = idx >> 6, rem = idx & 63;
        int lane = rem >> 1, half = rem & 1;
        int kstep = s / NT, nt = s - kstep * NT;
        int kk = kstep * 8 + (lane & 3) + half * 4;
        int nn = nt * 8 + (lane >> 2);
        float v = (nn < Nreal) ? W[kk * Nreal + nn] : 0.0f;
        dst[s * 64 + lane * 2 + half] = f2tf32(v);
    }
}

__global__ void prep_kernel(const float* __restrict__ W1, const float* __restrict__ W2,
                            const float* __restrict__ W3, const float* __restrict__ W4,
                            const float* __restrict__ W5) {
    int tid = blockIdx.x * blockDim.x + threadIdx.x;
    int ntot = gridDim.x * blockDim.x;
    stage_section(g_wfrag + W1F, W1, 64, 4, 8, tid, ntot);
    stage_section(g_wfrag + W2F, W2, 16, 8, 2, tid, ntot);
    stage_section(g_wfrag + W3F, W3, 64, 4, 8, tid, ntot);
    stage_section(g_wfrag + W4F, W4, 64, 8, 8, tid, ntot);
    stage_section(g_wfrag + W5F, W5, 3, 8, 1, tid, ntot);
}

// ---------------- layer cores ----------------
template <int KT, int NT, int STRIDE>
__device__ __forceinline__ void run_layer(const uint32_t* __restrict__ sA,
                                          const uint2* __restrict__ bfrag,
                                          const float* __restrict__ bias,
                                          int mrow0, int g, int tg, int lane,
                                          float (&acc)[2][NT][4]) {
#pragma unroll
    for (int m = 0; m < 2; m++)
#pragma unroll
        for (int nn = 0; nn < NT; nn++) {
            float2 bb = ((const float2*)bias)[nn * 4 + tg];
            acc[m][nn][0] = bb.x; acc[m][nn][1] = bb.y;
            acc[m][nn][2] = bb.x; acc[m][nn][3] = bb.y;
        }
#pragma unroll
    for (int k = 0; k < KT; k++) {
        uint2 bf[NT];
#pragma unroll
        for (int nn = 0; nn < NT; nn++)
            bf[nn] = bfrag[(k * NT + nn) * 32 + lane];
#pragma unroll
        for (int m = 0; m < 2; m++) {
            const uint32_t* ap = sA + (mrow0 + m * 16 + g) * STRIDE + k * 8 + tg;
            uint32_t a0 = ap[0];
            uint32_t a1 = ap[8 * STRIDE];
            uint32_t a2 = ap[4];
            uint32_t a3 = ap[8 * STRIDE + 4];
#pragma unroll
            for (int nn = 0; nn < NT; nn++)
                mma_tf32(acc[m][nn], a0, a1, a2, a3, bf[nn].x, bf[nn].y);
        }
    }
}

// L1: A-fragments straight from gmem position [n,32]
__device__ __forceinline__ void run_layer1(const float* __restrict__ pos, int n,
                                           int rowbase,
                                           const uint2* __restrict__ bfrag,
                                           const float* __restrict__ bias,
                                           int g, int tg, int lane,
                                           float (&acc)[2][8][4]) {
#pragma unroll
    for (int m = 0; m < 2; m++)
#pragma unroll
        for (int nn = 0; nn < 8; nn++) {
            float2 bb = ((const float2*)bias)[nn * 4 + tg];
            acc[m][nn][0] = bb.x; acc[m][nn][1] = bb.y;
            acc[m][nn][2] = bb.x; acc[m][nn][3] = bb.y;
        }
    int r0a = rowbase + g;          if (r0a >= n) r0a = n - 1;
    int r0b = rowbase + g + 8;      if (r0b >= n) r0b = n - 1;
    int r1a = rowbase + 16 + g;     if (r1a >= n) r1a = n - 1;
    int r1b = rowbase + 24 + g;     if (r1b >= n) r1b = n - 1;
    const float* p0a = pos + (size_t)r0a * 32 + tg;
    const float* p0b = pos + (size_t)r0b * 32 + tg;
    const float* p1a = pos + (size_t)r1a * 32 + tg;
    const float* p1b = pos + (size_t)r1b * 32 + tg;
#pragma unroll
    for (int k = 0; k < 4; k++) {
        uint2 bf[8];
#pragma unroll
        for (int nn = 0; nn < 8; nn++)
            bf[nn] = bfrag[(k * 8 + nn) * 32 + lane];
        {
            uint32_t a0 = f2tf32(p0a[k * 8]);
            uint32_t a1 = f2tf32(p0b[k * 8]);
            uint32_t a2 = f2tf32(p0a[k * 8 + 4]);
            uint32_t a3 = f2tf32(p0b[k * 8 + 4]);
#pragma unroll
            for (int nn = 0; nn < 8; nn++)
                mma_tf32(acc[0][nn], a0, a1, a2, a3, bf[nn].x, bf[nn].y);
        }
        {
            uint32_t a0 = f2tf32(p1a[k * 8]);
            uint32_t a1 = f2tf32(p1b[k * 8]);
            uint32_t a2 = f2tf32(p1a[k * 8 + 4]);
            uint32_t a3 = f2tf32(p1b[k * 8 + 4]);
#pragma unroll
            for (int nn = 0; nn < 8; nn++)
                mma_tf32(acc[1][nn], a0, a1, a2, a3, bf[nn].x, bf[nn].y);
        }
    }
}

template <int NT>
__device__ __forceinline__ void epi_relu_store(float (&acc)[2][NT][4],
                                               uint32_t* dst, int mrow0,
                                               int g, int tg) {
#pragma unroll
    for (int m = 0; m < 2; m++)
#pragma unroll
        for (int nn = 0; nn < NT; nn++) {
            int r0 = mrow0 + m * 16 + g;
            uint2 lo, hi;
            lo.x = f2tf32(fmaxf(acc[m][nn][0], 0.0f));
            lo.y = f2tf32(fmaxf(acc[m][nn][1], 0.0f));
            hi.x = f2tf32(fmaxf(acc[m][nn][2], 0.0f));
            hi.y = f2tf32(fmaxf(acc[m][nn][3], 0.0f));
            *(uint2*)(dst + r0 * HS + nn * 8 + 2 * tg) = lo;
            *(uint2*)(dst + (r0 + 8) * HS + nn * 8 + 2 * tg) = hi;
        }
}

__global__ void __launch_bounds__(THREADS, 2)
nerf_mma_kernel(const float* __restrict__ position,
                const float* __restrict__ direction,
                const float* __restrict__ b1, const float* __restrict__ b2,
                const float* __restrict__ b3, const float* __restrict__ b4,
                const float* __restrict__ b5,
                float* __restrict__ out, int n) {
    extern __shared__ float smf[];
    uint32_t* smu = (uint32_t*)smf;

    const int tid = threadIdx.x;
    const int lane = tid & 31;
    const int wid = tid >> 5;
    const int g = lane >> 2;
    const int tg = lane & 3;

    // biases
    if (tid < 64) smf[OFF_B1 + tid] = b1[tid];
    if (tid < 16) smf[OFF_B2 + tid] = b2[tid];
    if (tid < 64) smf[OFF_B3 + tid] = b3[tid];
    if (tid < 64) smf[OFF_B4 + tid] = b4[tid];
    if (tid < 8)  smf[OFF_B5 + tid] = (tid < 3) ? b5[tid] : 0.0f;
    __syncthreads();

    const int base = blockIdx.x * ROWS;
    uint32_t* IN = smu + OFF_IN;   // cols 0-15 dens, 16-31 SH
    uint32_t* H  = smu + OFF_H;

    // ---- SH(dir) for own row -> IN cols 16..31 (own-warp rows only) ----
    {
        int r = base + tid; if (r >= n) r = n - 1;
        const float* dp = direction + (size_t)r * 3;
        float x = dp[0], y = dp[1], z = dp[2];
        float xx = x * x, yy = y * y, zz = z * z;
        uint32_t* row = IN + tid * INS + 16;
        row[0]  = f2tf32(0.28209479177387814f);
        row[1]  = f2tf32(0.4886025119029199f * y);
        row[2]  = f2tf32(0.4886025119029199f * z);
        row[3]  = f2tf32(0.4886025119029199f * x);
        row[4]  = f2tf32(1.0925484305920792f * x * y);
        row[5]  = f2tf32(1.0925484305920792f * y * z);
        row[6]  = f2tf32(0.9461746957575601f * zz - 0.31539156525252f);
        row[7]  = f2tf32(1.0925484305920792f * x * z);
        row[8]  = f2tf32(0.5462742152960396f * (xx - yy));
        row[9]  = f2tf32(0.5900435899266435f * y * (3.0f * xx - yy));
        row[10] = f2tf32(2.890611442640554f * x * y * z);
        row[11] = f2tf32(0.4570457994644658f * y * (5.0f * zz - 1.0f));
        row[12] = f2tf32(0.3731763325901154f * z * (5.0f * zz - 3.0f));
        row[13] = f2tf32(0.4570457994644658f * x * (5.0f * zz - 1.0f));
        row[14] = f2tf32(1.445305721320277f * z * (xx - yy));
        row[15] = f2tf32(0.5900435899266435f * x * (xx - 3.0f * yy));
    }
    __syncwarp();

    const int mrow0 = wid * 32;
    const uint2* fr = (const uint2*)g_wfrag;

    // ---- L1: pos @ W1 -> H (relu) ----
    {
        float acc[2][8][4];
        run_layer1(position, n, base + mrow0, fr + (W1F >> 1), smf + OFF_B1,
                   g, tg, lane, acc);
        epi_relu_store<8>(acc, H, mrow0, g, tg);
    }
    __syncwarp();

    // ---- L2: H @ W2 -> density: gmem + IN cols 0..15 ----
    {
        float acc[2][2][4];
        run_layer<8, 2, HS>(H, fr + (W2F >> 1), smf + OFF_B2, mrow0, g, tg, lane, acc);
#pragma unroll
        for (int m = 0; m < 2; m++)
#pragma unroll
            for (int nn = 0; nn < 2; nn++) {
                int r0 = mrow0 + m * 16 + g;
                int gr0 = base + r0;
                float2 lo = make_float2(acc[m][nn][0], acc[m][nn][1]);
                float2 hi = make_float2(acc[m][nn][2], acc[m][nn][3]);
                if (gr0 < n)
                    *(float2*)(out + (size_t)gr0 * 16 + nn * 8 + 2 * tg) = lo;
                if (gr0 + 8 < n)
                    *(float2*)(out + (size_t)(gr0 + 8) * 16 + nn * 8 + 2 * tg) = hi;
                uint2 ulo, uhi;
                ulo.x = f2tf32(lo.x); ulo.y = f2tf32(lo.y);
                uhi.x = f2tf32(hi.x); uhi.y = f2tf32(hi.y);
                *(uint2*)(IN + r0 * INS + nn * 8 + 2 * tg) = ulo;
                *(uint2*)(IN + (r0 + 8) * INS + nn * 8 + 2 * tg) = uhi;
            }
    }
    __syncwarp();

    // ---- L3: IN (dens||SH) @ W3 -> H (relu) ----
    {
        float acc[2][8][4];
        run_layer<4, 8, INS>(IN, fr + (W3F >> 1), smf + OFF_B3, mrow0, g, tg, lane, acc);
        epi_relu_store<8>(acc, H, mrow0, g, tg);
    }
    __syncwarp();

    // ---- L4: H @ W4 -> H in place (safe: all warp reads precede writes) ----
    {
        float acc[2][8][4];
        run_layer<8, 8, HS>(H, fr + (W4F >> 1), smf + OFF_B4, mrow0, g, tg, lane, acc);
        epi_relu_store<8>(acc, H, mrow0, g, tg);
    }
    __syncwarp();

    // ---- L5: H @ W5 -> color (sigmoid) ----
    {
        float acc[2][1][4];
        run_layer<8, 1, HS>(H, fr + (W5F >> 1), smf + OFF_B5, mrow0, g, tg, lane, acc);
        float* co = out + (size_t)n * 16;
#pragma unroll
        for (int m = 0; m < 2; m++) {
            int gr0 = base + mrow0 + m * 16 + g;
            float s0 = 1.0f / (1.0f + __expf(-acc[m][0][0]));
            float s1 = 1.0f / (1.0f + __expf(-acc[m][0][1]));
            float s2 = 1.0f / (1.0f + __expf(-acc[m][0][2]));
            float s3 = 1.0f / (1.0f + __expf(-acc[m][0][3]));
            if (tg == 0) {
                if (gr0 < n)     { co[(size_t)gr0 * 3 + 0] = s0;
                                   co[(size_t)gr0 * 3 + 1] = s1; }
                if (gr0 + 8 < n) { co[(size_t)(gr0 + 8) * 3 + 0] = s2;
                                   co[(size_t)(gr0 + 8) * 3 + 1] = s3; }
            } else if (tg == 1) {
                if (gr0 < n)     co[(size_t)gr0 * 3 + 2] = s0;
                if (gr0 + 8 < n) co[(size_t)(gr0 + 8) * 3 + 2] = s2;
            }
        }
    }
}

extern "C" void kernel_launch(void* const* d_in, const int* in_sizes, int n_in,
                              void* d_out, int out_size) {
    const float* position = (const float*)d_in[0];
    const float* direction = (const float*)d_in[1];
    const float* W1 = (const float*)d_in[2];
    const float* b1 = (const float*)d_in[3];
    const float* W2 = (const float*)d_in[4];
    const float* b2 = (const float*)d_in[5];
    const float* W3 = (const float*)d_in[6];
    const float* b3 = (const float*)d_in[7];
    const float* W4 = (const float*)d_in[8];
    const float* b4 = (const float*)d_in[9];
    const float* W5 = (const float*)d_in[10];
    const float* b5 = (const float*)d_in[11];
    float* out = (float*)d_out;

    int n = in_sizes[0] / 32;
    int ntiles = (n + ROWS - 1) / ROWS;
    if (ntiles <= 0) return;
    size_t smem_bytes = (size_t)SMEM_FLOATS * sizeof(float);

    cudaFuncSetAttribute(nerf_mma_kernel,
                         cudaFuncAttributeMaxDynamicSharedMemorySize,
                         (int)smem_bytes);
    prep_kernel<<<40, 256>>>(W1, W2, W3, W4, W5);
    nerf_mma_kernel<<<ntiles, THREADS, smem_bytes>>>(position, direction,
                                                     b1, b2, b3, b4, b5,
                                                     out, n);
}